// round 2
// baseline (speedup 1.0000x reference)
#include <cuda_runtime.h>
#include <math.h>
#include <stdint.h>

#define LSEQ 4096
#define DM   256
#define DI   512
#define DS   16
#define NB   2

// ---------------- scratch (device globals; no runtime alloc allowed) ----------------
__device__ float g_xc [NB*DM*LSEQ];   // (b, c=256, l)  concat of up + skip
__device__ float g_xi [NB*DI*LSEQ];   // (b, d=512, l)  pre-conv x branch
__device__ float g_z  [NB*LSEQ*DI];   // (b, l, d)      gate branch (pre-silu)
__device__ float g_u  [NB*LSEQ*DI];   // (b, l, d)      post conv1d + silu
__device__ float g_dbc[NB*LSEQ*48];   // (b, l, 48)     [dt_rank | B | C]
__device__ float g_dt [NB*LSEQ*DI];   // (b, l, d)      softplus(dt)
__device__ float g_y  [NB*LSEQ*DI];   // (b, l, d)      scan output * silu(z)
__device__ float g_xr [NB*DM*LSEQ];   // (b, c, l)      xc + mamba out
__device__ float g_y2 [NB*128*LSEQ];  // (b, o=128, l)  conv3x3 out (pre-BN)
__device__ float g_mv [256];          // mean[128], var[128]

// ---------------- generic 64x64x16 tiled fp32 GEMM with epilogue functor ----------------
// C[m,n] = sum_k A[m,k]*B[k,n]
// TA: A[m,k] = A[k*lda + m] (m contiguous), else A[m*lda + k] (k contiguous)
// TB: B[k,n] = B[n*ldb + k] (k contiguous), else B[k*ldb + n] (n contiguous)
template<bool TA, bool TB, class Epi>
__global__ __launch_bounds__(256)
void gemm_k(const float* __restrict__ A, int lda, long sA,
            const float* __restrict__ B, int ldb, long sB,
            int M, int N, int K, Epi epi)
{
    __shared__ float As[16][68];
    __shared__ float Bs[16][68];
    const int tid = threadIdx.x;
    const int bz  = blockIdx.z;
    const float* Ab = A + (size_t)bz * sA;
    const float* Bb = B + (size_t)bz * sB;
    const int m0 = blockIdx.y * 64;
    const int n0 = blockIdx.x * 64;
    const int tx = tid & 15, ty = tid >> 4;

    float acc[4][4];
#pragma unroll
    for (int i = 0; i < 4; i++)
#pragma unroll
        for (int j = 0; j < 4; j++) acc[i][j] = 0.f;

    for (int k0 = 0; k0 < K; k0 += 16) {
        if (TA) {
            int k  = tid >> 4;
            int mq = (tid & 15) << 2;
            float4 v = *reinterpret_cast<const float4*>(Ab + (size_t)(k0 + k)*lda + m0 + mq);
            *reinterpret_cast<float4*>(&As[k][mq]) = v;
        } else {
            int m  = tid >> 2;
            int kq = (tid & 3) << 2;
            float4 v = *reinterpret_cast<const float4*>(Ab + (size_t)(m0 + m)*lda + k0 + kq);
            As[kq+0][m] = v.x; As[kq+1][m] = v.y; As[kq+2][m] = v.z; As[kq+3][m] = v.w;
        }
        if (TB) {
            int nn = tid >> 2;
            int kq = (tid & 3) << 2;
            float4 v = make_float4(0.f,0.f,0.f,0.f);
            if (n0 + nn < N)
                v = *reinterpret_cast<const float4*>(Bb + (size_t)(n0 + nn)*ldb + k0 + kq);
            Bs[kq+0][nn] = v.x; Bs[kq+1][nn] = v.y; Bs[kq+2][nn] = v.z; Bs[kq+3][nn] = v.w;
        } else {
            int k  = tid >> 4;
            int nq = (tid & 15) << 2;
            float4 v = *reinterpret_cast<const float4*>(Bb + (size_t)(k0 + k)*ldb + n0 + nq);
            *reinterpret_cast<float4*>(&Bs[k][nq]) = v;
        }
        __syncthreads();
#pragma unroll
        for (int kk = 0; kk < 16; ++kk) {
            float4 a4 = *reinterpret_cast<const float4*>(&As[kk][ty << 2]);
            float4 b4 = *reinterpret_cast<const float4*>(&Bs[kk][tx << 2]);
            float a[4] = {a4.x, a4.y, a4.z, a4.w};
            float b[4] = {b4.x, b4.y, b4.z, b4.w};
#pragma unroll
            for (int i = 0; i < 4; i++)
#pragma unroll
                for (int j = 0; j < 4; j++) acc[i][j] += a[i] * b[j];
        }
        __syncthreads();
    }
#pragma unroll
    for (int i = 0; i < 4; i++) {
        int mi = m0 + (ty << 2) + i;
#pragma unroll
        for (int j = 0; j < 4; j++) {
            int ni = n0 + (tx << 2) + j;
            if (mi < M && ni < N) epi(bz, mi, ni, acc[i][j]);
        }
    }
}

// ---------------- epilogues ----------------
struct EpiUp {
    float* xc; const float* up_b;
    __device__ void operator()(int b, int m, int n, float v) const {
        int o = m >> 2, i = (m >> 1) & 1, j = m & 1;
        int h = n >> 5, w = n & 31;
        xc[((size_t)b*DM + o)*LSEQ + (2*h + i)*64 + (2*w + j)] = v + up_b[o];
    }
};
struct EpiXZ {
    float* xi; float* z;
    __device__ void operator()(int b, int m, int n, float v) const {
        if (n < DI) xi[((size_t)b*DI + n)*LSEQ + m] = v;
        else        z [((size_t)b*LSEQ + m)*DI + (n - DI)] = v;
    }
};
struct EpiDbc {
    float* dbc;
    __device__ void operator()(int, int m, int n, float v) const {
        dbc[(size_t)m*48 + n] = v;
    }
};
struct EpiDt {
    float* dt; const float* bias;
    __device__ void operator()(int, int m, int n, float v) const {
        float x = v + bias[n];
        float sp = (x > 20.f) ? x : log1pf(__expf(x));
        dt[(size_t)m*DI + n] = sp;
    }
};
struct EpiOut {
    const float* xc; float* xr;
    __device__ void operator()(int b, int m, int n, float v) const {
        size_t idx = ((size_t)b*DM + n)*LSEQ + m;
        xr[idx] = xc[idx] + v;
    }
};

// ---------------- skip concat copy ----------------
__global__ void copy_skip(const float* __restrict__ skip, float* __restrict__ xc) {
    int idx = blockIdx.x * blockDim.x + threadIdx.x;
    int total = NB * 128 * LSEQ;
    if (idx >= total) return;
    int b = idx / (128 * LSEQ);
    int rem = idx - b * (128 * LSEQ);
    xc[((size_t)b*DM + 128)*LSEQ + rem] = skip[idx];
}

// ---------------- depthwise causal conv1d + silu, transpose (b,d,l)->(b,l,d) ----------------
__global__ __launch_bounds__(256)
void conv1d_kernel(const float* __restrict__ xi, const float* __restrict__ w,
                   const float* __restrict__ bias, float* __restrict__ u)
{
    __shared__ float s[32][37];
    int b  = blockIdx.z;
    int d0 = blockIdx.y * 32;
    int l0 = blockIdx.x * 32;
    int tid = threadIdx.x;
    for (int e = tid; e < 32*36; e += 256) {
        int dd = e / 36, li = e % 36;
        int l = l0 - 3 + li;
        float v = (l >= 0 && l < LSEQ) ? xi[((size_t)b*DI + d0 + dd)*LSEQ + l] : 0.f;
        s[dd][li] = v;
    }
    __syncthreads();
    int dd = tid & 31, lg = tid >> 5;
    float w0 = w[(d0+dd)*4 + 0], w1 = w[(d0+dd)*4 + 1];
    float w2 = w[(d0+dd)*4 + 2], w3 = w[(d0+dd)*4 + 3];
    float bv = bias[d0+dd];
#pragma unroll
    for (int li = lg; li < 32; li += 8) {
        float a = s[dd][li]*w0 + s[dd][li+1]*w1 + s[dd][li+2]*w2 + s[dd][li+3]*w3 + bv;
        float sv = a / (1.f + __expf(-a));
        u[((size_t)b*LSEQ + l0 + li)*DI + d0 + dd] = sv;
    }
}

// ---------------- selective scan: warp = 2 channels, 16 lanes = 16 states ----------------
__global__ __launch_bounds__(128)
void scan_kernel(const float* __restrict__ dt, const float* __restrict__ u,
                 const float* __restrict__ dbc, const float* __restrict__ z,
                 const float* __restrict__ A_log, const float* __restrict__ Dp,
                 float* __restrict__ y)
{
    int tid  = threadIdx.x;
    int lane = tid & 31;
    int n    = lane & 15;
    int half = lane >> 4;
    int warp = tid >> 5;
    int gch  = blockIdx.x * 8 + warp * 2 + half;   // 0 .. NB*DI-1
    int b = gch >> 9;
    int d = gch & (DI - 1);

    float A  = -__expf(A_log[d*DS + n]);
    float Dv = Dp[d];
    float h  = 0.f;

    const float* dt_b  = dt  + (size_t)b*LSEQ*DI + d;
    const float* u_b   = u   + (size_t)b*LSEQ*DI + d;
    const float* z_b   = z   + (size_t)b*LSEQ*DI + d;
    const float* dbc_b = dbc + (size_t)b*LSEQ*48;
    float*       y_b   = y   + (size_t)b*LSEQ*DI + d;

#pragma unroll 4
    for (int l = 0; l < LSEQ; ++l) {
        float dtv = dt_b[(size_t)l*DI];
        float uv  = u_b [(size_t)l*DI];
        float bn  = dbc_b[l*48 + 16 + n];
        float cn  = dbc_b[l*48 + 32 + n];
        float dA  = __expf(dtv * A);
        h = dA * h + (dtv * uv) * bn;
        float yp = h * cn;
        yp += __shfl_xor_sync(0xffffffffu, yp, 1);
        yp += __shfl_xor_sync(0xffffffffu, yp, 2);
        yp += __shfl_xor_sync(0xffffffffu, yp, 4);
        yp += __shfl_xor_sync(0xffffffffu, yp, 8);
        if (n == 0) {
            float yv = yp + uv * Dv;
            float zv = z_b[(size_t)l*DI];
            float sg = zv / (1.f + __expf(-zv));
            y_b[(size_t)l*DI] = yv * sg;
        }
    }
}

// ---------------- 3x3 conv (128 out, 256 in, pad 1), smem tiled ----------------
__global__ __launch_bounds__(256)
void conv3_kernel(const float* __restrict__ xr, const float* __restrict__ W,
                  const float* __restrict__ bias, float* __restrict__ y2)
{
    __shared__ float in_s[16][18][19];
    __shared__ float w_s[32][16][9];
    int b  = blockIdx.z;
    int o0 = blockIdx.y * 32;
    int pt = blockIdx.x;            // 16 tiles of 16x16 pixels
    int h0 = (pt >> 2) * 16;
    int w0 = (pt & 3) * 16;
    int tid = threadIdx.x;
    int wo  = tid & 63;
    int og  = tid >> 6;             // 0..3
    int prow  = wo >> 2;            // 0..15
    int pcol0 = (wo & 3) << 2;      // 0,4,8,12

    float acc[8][4];
#pragma unroll
    for (int i = 0; i < 8; i++)
#pragma unroll
        for (int j = 0; j < 4; j++) acc[i][j] = 0.f;

    const float* xrb = xr + (size_t)b * DM * LSEQ;
    for (int c0 = 0; c0 < 256; c0 += 16) {
        for (int e = tid; e < 16*18*18; e += 256) {
            int c = e / 324, r = (e % 324) / 18, cc = e % 18;
            int h = h0 + r - 1, w = w0 + cc - 1;
            float v = 0.f;
            if (h >= 0 && h < 64 && w >= 0 && w < 64)
                v = xrb[(size_t)(c0 + c)*LSEQ + h*64 + w];
            in_s[c][r][cc] = v;
        }
        for (int e = tid; e < 32*16*9; e += 256) {
            int o = e / 144, rest = e % 144, c = rest / 9, t = rest % 9;
            w_s[o][c][t] = W[(size_t)(o0 + o)*2304 + (c0 + c)*9 + t];
        }
        __syncthreads();
#pragma unroll 1
        for (int c = 0; c < 16; ++c) {
#pragma unroll
            for (int t = 0; t < 9; ++t) {
                int di = t / 3, dj = t % 3;
                float iv[4];
#pragma unroll
                for (int j = 0; j < 4; ++j) iv[j] = in_s[c][prow + di][pcol0 + dj + j];
#pragma unroll
                for (int oi = 0; oi < 8; ++oi) {
                    float wv = w_s[og*8 + oi][c][t];
#pragma unroll
                    for (int j = 0; j < 4; ++j) acc[oi][j] += wv * iv[j];
                }
            }
        }
        __syncthreads();
    }
#pragma unroll
    for (int oi = 0; oi < 8; ++oi) {
        int o = o0 + og*8 + oi;
        float bv = bias[o];
#pragma unroll
        for (int j = 0; j < 4; ++j)
            y2[((size_t)b*128 + o)*LSEQ + (h0 + prow)*64 + (w0 + pcol0 + j)] = acc[oi][j] + bv;
    }
}

// ---------------- batchnorm stats + apply + gelu ----------------
__global__ void bn_stats(const float* __restrict__ y2, float* __restrict__ mv) {
    int o = blockIdx.x;
    float s = 0.f, s2 = 0.f;
    for (int i = threadIdx.x; i < NB*LSEQ; i += 256) {
        int b = i >> 12, l = i & (LSEQ - 1);
        float v = y2[((size_t)b*128 + o)*LSEQ + l];
        s += v; s2 += v*v;
    }
    __shared__ float sh0[256], sh1[256];
    sh0[threadIdx.x] = s; sh1[threadIdx.x] = s2;
    __syncthreads();
    for (int st = 128; st > 0; st >>= 1) {
        if (threadIdx.x < st) {
            sh0[threadIdx.x] += sh0[threadIdx.x + st];
            sh1[threadIdx.x] += sh1[threadIdx.x + st];
        }
        __syncthreads();
    }
    if (threadIdx.x == 0) {
        float inv = 1.f / (NB * LSEQ);
        float mu = sh0[0] * inv;
        float var = sh1[0] * inv - mu * mu;
        mv[o] = mu; mv[128 + o] = var;
    }
}

__global__ void bn_apply(const float* __restrict__ y2, const float* __restrict__ mv,
                         const float* __restrict__ gamma, const float* __restrict__ beta,
                         float* __restrict__ out)
{
    int idx = blockIdx.x * blockDim.x + threadIdx.x;
    if (idx >= NB*128*LSEQ) return;
    int o = (idx >> 12) & 127;
    float mu = mv[o], var = mv[128 + o];
    float v = (y2[idx] - mu) * rsqrtf(var + 1e-5f) * gamma[o] + beta[o];
    out[idx] = 0.5f * v * (1.f + erff(v * 0.70710678118654752440f));
}

// ---------------- launch ----------------
extern "C" void kernel_launch(void* const* d_in, const int* in_sizes, int n_in,
                              void* d_out, int out_size)
{
    const float* x        = (const float*)d_in[0];
    const float* skip     = (const float*)d_in[1];
    const float* up_w     = (const float*)d_in[2];
    const float* up_b     = (const float*)d_in[3];
    const float* in_proj  = (const float*)d_in[4];
    const float* c1w      = (const float*)d_in[5];
    const float* c1b      = (const float*)d_in[6];
    const float* xproj    = (const float*)d_in[7];
    const float* dtw      = (const float*)d_in[8];
    const float* dtb      = (const float*)d_in[9];
    const float* A_log    = (const float*)d_in[10];
    const float* Dp       = (const float*)d_in[11];
    const float* outw     = (const float*)d_in[12];
    const float* cw       = (const float*)d_in[13];
    const float* cb       = (const float*)d_in[14];
    const float* bng      = (const float*)d_in[15];
    const float* bnb      = (const float*)d_in[16];
    float* out = (float*)d_out;

    float *xc, *xi, *z, *u, *dbc, *dtv, *y, *xr, *y2, *mv;
    cudaGetSymbolAddress((void**)&xc,  g_xc);
    cudaGetSymbolAddress((void**)&xi,  g_xi);
    cudaGetSymbolAddress((void**)&z,   g_z);
    cudaGetSymbolAddress((void**)&u,   g_u);
    cudaGetSymbolAddress((void**)&dbc, g_dbc);
    cudaGetSymbolAddress((void**)&dtv, g_dt);
    cudaGetSymbolAddress((void**)&y,   g_y);
    cudaGetSymbolAddress((void**)&xr,  g_xr);
    cudaGetSymbolAddress((void**)&y2,  g_y2);
    cudaGetSymbolAddress((void**)&mv,  g_mv);

    // 1) upsample as GEMM: C[512, 1024] = up_w^T(512x256) * x[b](256x1024)
    gemm_k<true, false, EpiUp><<<dim3(16, 8, NB), 256>>>(
        up_w, 512, 0, x, 1024, (long)256*1024, 512, 1024, 256, EpiUp{xc, up_b});

    // 2) skip concat
    copy_skip<<<(NB*128*LSEQ + 255)/256, 256>>>(skip, xc);

    // 3) in_proj GEMM: per batch C[4096, 1024] = xc^T(l,c) * in_proj^T
    gemm_k<true, true, EpiXZ><<<dim3(16, 64, NB), 256>>>(
        xc, LSEQ, (long)DM*LSEQ, in_proj, DM, 0, LSEQ, 2*DI, DM, EpiXZ{xi, z});

    // 4) depthwise conv1d + silu
    conv1d_kernel<<<dim3(LSEQ/32, DI/32, NB), 256>>>(xi, c1w, c1b, u);

    // 5) x_proj GEMM: C[8192, 48] = u(8192x512) * xproj^T
    gemm_k<false, true, EpiDbc><<<dim3(1, 128, 1), 256>>>(
        u, DI, 0, xproj, DI, 0, NB*LSEQ, 48, DI, EpiDbc{dbc});

    // 6) dt GEMM + softplus: C[8192, 512] = dbc[:, :16] * dtw^T
    gemm_k<false, true, EpiDt><<<dim3(8, 128, 1), 256>>>(
        dbc, 48, 0, dtw, 16, 0, NB*LSEQ, DI, 16, EpiDt{dtv, dtb});

    // 7) selective scan + D skip + silu(z) gating
    scan_kernel<<<NB*DI/8, 128>>>(dtv, u, dbc, z, A_log, Dp, y);

    // 8) out_proj GEMM + residual into xr (transposed write)
    gemm_k<false, true, EpiOut><<<dim3(4, 64, NB), 256>>>(
        y, DI, (long)LSEQ*DI, outw, DI, 0, LSEQ, DM, DI, EpiOut{xc, xr});

    // 9) 3x3 conv
    conv3_kernel<<<dim3(16, 4, NB), 256>>>(xr, cw, cb, y2);

    // 10) batchnorm stats
    bn_stats<<<128, 256>>>(y2, mv);

    // 11) batchnorm apply + gelu
    bn_apply<<<(NB*128*LSEQ + 255)/256, 256>>>(y2, mv, bng, bnb, out);
}

// round 3
// speedup vs baseline: 3.4660x; 3.4660x over previous
#include <cuda_runtime.h>
#include <math.h>
#include <stdint.h>

#define LSEQ 4096
#define DM   256
#define DI   512
#define DS   16
#define NB   2
#define NCH  64   // scan chunks
#define CT   64   // chunk length

// ---------------- scratch (device globals; no runtime alloc allowed) ----------------
__device__ float g_xc [NB*DM*LSEQ];    // (b, c=256, l)  concat of up + skip
__device__ float g_xi [NB*DI*LSEQ];    // (b, d, l)  pre-conv x branch
__device__ float g_z  [NB*DI*LSEQ];    // (b, d, l)  gate branch (pre-silu)
__device__ float g_u  [NB*DI*LSEQ];    // (b, d, l)  post conv1d + silu
__device__ float g_dbc[48*NB*LSEQ];    // (j=48, b*l) transposed [dt_rank | B | C]
__device__ float g_dt [NB*DI*LSEQ];    // (b, d, l)  softplus(dt)
__device__ float g_y  [NB*DI*LSEQ];    // (b, d, l)  scan output * silu(z)
__device__ float g_xr [NB*DM*LSEQ];    // (b, c, l)  xc + mamba out
__device__ float g_y2 [NB*128*LSEQ];   // (b, o, l)  conv3x3 out (pre-BN)
__device__ float g_mv [256];           // mean[128], var[128]
__device__ float g_S  [NB*DI*NCH*DS];  // per-chunk local end state
__device__ float g_hs [NB*DI*NCH*DS];  // per-chunk start state
__device__ float g_sd [NB*DI*NCH];     // per-chunk sum(dt)

// ================= fast 128x128x8 double-buffered fp32 GEMM =================
// C[m,n] = sum_k A[m,k]*B[k,n];  A is always k-major: A[m,k] = A[k*lda + m]
// TB: B[k,n] = B[n*ldb + k]  else B[k*ldb + n]
// Requires M%128==0, N%128==0, K%8==0.
template<bool TB, class Epi>
__global__ __launch_bounds__(256)
void gemm128(const float* __restrict__ A, int lda, long sA,
             const float* __restrict__ B, int ldb, long sB,
             int M, int N, int K, Epi epi)
{
    __shared__ float As[2][8][128];
    __shared__ float Bs[2][8][128];
    const int tid = threadIdx.x;
    const int bz  = blockIdx.z;
    const float* Ab = A + (size_t)bz * sA;
    const float* Bb = B + (size_t)bz * sB;
    const int m0 = blockIdx.y * 128;
    const int n0 = blockIdx.x * 128;
    const int tx = tid & 15, ty = tid >> 4;

    // A load coords: row k (8), col m (128)
    const int ak = tid >> 5;
    const int am = (tid & 31) << 2;
    // B load coords (TB=true): n (128), kq in {0,4}
    const int bn_ = tid >> 1;
    const int bkq = (tid & 1) << 2;

    float acc[8][8];
#pragma unroll
    for (int i = 0; i < 8; i++)
#pragma unroll
        for (int j = 0; j < 8; j++) acc[i][j] = 0.f;

    const int nt = K >> 3;

    // prologue: load tile 0 straight into smem buffer 0
    {
        float4 va = *reinterpret_cast<const float4*>(Ab + (size_t)ak*lda + m0 + am);
        *reinterpret_cast<float4*>(&As[0][ak][am]) = va;
        if (TB) {
            float4 vb = *reinterpret_cast<const float4*>(Bb + (size_t)(n0 + bn_)*ldb + bkq);
            Bs[0][bkq+0][bn_] = vb.x; Bs[0][bkq+1][bn_] = vb.y;
            Bs[0][bkq+2][bn_] = vb.z; Bs[0][bkq+3][bn_] = vb.w;
        } else {
            float4 vb = *reinterpret_cast<const float4*>(Bb + (size_t)ak*ldb + n0 + am);
            *reinterpret_cast<float4*>(&Bs[0][ak][am]) = vb;
        }
    }
    __syncthreads();

    int buf = 0;
    for (int kt = 0; kt < nt; ++kt) {
        float4 pa, pb;
        const bool has = (kt + 1 < nt);
        if (has) {
            int k0 = (kt + 1) << 3;
            pa = *reinterpret_cast<const float4*>(Ab + (size_t)(k0 + ak)*lda + m0 + am);
            if (TB)
                pb = *reinterpret_cast<const float4*>(Bb + (size_t)(n0 + bn_)*ldb + k0 + bkq);
            else
                pb = *reinterpret_cast<const float4*>(Bb + (size_t)(k0 + ak)*ldb + n0 + am);
        }
#pragma unroll
        for (int kk = 0; kk < 8; ++kk) {
            float a[8], b[8];
            *reinterpret_cast<float4*>(&a[0]) = *reinterpret_cast<const float4*>(&As[buf][kk][ty << 2]);
            *reinterpret_cast<float4*>(&a[4]) = *reinterpret_cast<const float4*>(&As[buf][kk][64 + (ty << 2)]);
            *reinterpret_cast<float4*>(&b[0]) = *reinterpret_cast<const float4*>(&Bs[buf][kk][tx << 2]);
            *reinterpret_cast<float4*>(&b[4]) = *reinterpret_cast<const float4*>(&Bs[buf][kk][64 + (tx << 2)]);
#pragma unroll
            for (int i = 0; i < 8; i++)
#pragma unroll
                for (int j = 0; j < 8; j++) acc[i][j] += a[i] * b[j];
        }
        if (has) {
            int nb = buf ^ 1;
            *reinterpret_cast<float4*>(&As[nb][ak][am]) = pa;
            if (TB) {
                Bs[nb][bkq+0][bn_] = pb.x; Bs[nb][bkq+1][bn_] = pb.y;
                Bs[nb][bkq+2][bn_] = pb.z; Bs[nb][bkq+3][bn_] = pb.w;
            } else {
                *reinterpret_cast<float4*>(&Bs[nb][ak][am]) = pb;
            }
            __syncthreads();
            buf = nb;
        }
    }

#pragma unroll
    for (int i = 0; i < 8; i++) {
        int mi = m0 + ((i < 4) ? (ty << 2) + i : 64 + (ty << 2) + (i - 4));
#pragma unroll
        for (int j = 0; j < 8; j++) {
            int ni = n0 + ((j < 4) ? (tx << 2) + j : 64 + (tx << 2) + (j - 4));
            epi(bz, mi, ni, acc[i][j]);
        }
    }
}

// ================= small generic 64x64x16 GEMM (for skinny shapes) =================
template<bool TA, bool TB, class Epi>
__global__ __launch_bounds__(256)
void gemm_k(const float* __restrict__ A, int lda, long sA,
            const float* __restrict__ B, int ldb, long sB,
            int M, int N, int K, Epi epi)
{
    __shared__ float As[16][68];
    __shared__ float Bs[16][68];
    const int tid = threadIdx.x;
    const int bz  = blockIdx.z;
    const float* Ab = A + (size_t)bz * sA;
    const float* Bb = B + (size_t)bz * sB;
    const int m0 = blockIdx.y * 64;
    const int n0 = blockIdx.x * 64;
    const int tx = tid & 15, ty = tid >> 4;

    float acc[4][4];
#pragma unroll
    for (int i = 0; i < 4; i++)
#pragma unroll
        for (int j = 0; j < 4; j++) acc[i][j] = 0.f;

    for (int k0 = 0; k0 < K; k0 += 16) {
        if (TA) {
            int k  = tid >> 4;
            int mq = (tid & 15) << 2;
            float4 v = *reinterpret_cast<const float4*>(Ab + (size_t)(k0 + k)*lda + m0 + mq);
            *reinterpret_cast<float4*>(&As[k][mq]) = v;
        } else {
            int m  = tid >> 2;
            int kq = (tid & 3) << 2;
            float4 v = *reinterpret_cast<const float4*>(Ab + (size_t)(m0 + m)*lda + k0 + kq);
            As[kq+0][m] = v.x; As[kq+1][m] = v.y; As[kq+2][m] = v.z; As[kq+3][m] = v.w;
        }
        if (TB) {
            int nn = tid >> 2;
            int kq = (tid & 3) << 2;
            float4 v = make_float4(0.f,0.f,0.f,0.f);
            if (n0 + nn < N)
                v = *reinterpret_cast<const float4*>(Bb + (size_t)(n0 + nn)*ldb + k0 + kq);
            Bs[kq+0][nn] = v.x; Bs[kq+1][nn] = v.y; Bs[kq+2][nn] = v.z; Bs[kq+3][nn] = v.w;
        } else {
            int k  = tid >> 4;
            int nq = (tid & 15) << 2;
            float4 v = *reinterpret_cast<const float4*>(Bb + (size_t)(k0 + k)*ldb + n0 + nq);
            *reinterpret_cast<float4*>(&Bs[k][nq]) = v;
        }
        __syncthreads();
#pragma unroll
        for (int kk = 0; kk < 16; ++kk) {
            float4 a4 = *reinterpret_cast<const float4*>(&As[kk][ty << 2]);
            float4 b4 = *reinterpret_cast<const float4*>(&Bs[kk][tx << 2]);
            float a[4] = {a4.x, a4.y, a4.z, a4.w};
            float b[4] = {b4.x, b4.y, b4.z, b4.w};
#pragma unroll
            for (int i = 0; i < 4; i++)
#pragma unroll
                for (int j = 0; j < 4; j++) acc[i][j] += a[i] * b[j];
        }
        __syncthreads();
    }
#pragma unroll
    for (int i = 0; i < 4; i++) {
        int mi = m0 + (ty << 2) + i;
#pragma unroll
        for (int j = 0; j < 4; j++) {
            int ni = n0 + (tx << 2) + j;
            if (mi < M && ni < N) epi(bz, mi, ni, acc[i][j]);
        }
    }
}

// ---------------- epilogues ----------------
struct EpiUp {
    float* xc; const float* up_b;
    __device__ void operator()(int b, int m, int n, float v) const {
        int o = m >> 2, i = (m >> 1) & 1, j = m & 1;
        int h = n >> 5, w = n & 31;
        xc[((size_t)b*DM + o)*LSEQ + (2*h + i)*64 + (2*w + j)] = v + up_b[o];
    }
};
struct EpiXZ {  // xi, z both (b, d, l)
    float* xi; float* z;
    __device__ void operator()(int b, int m, int n, float v) const {
        if (n < DI) xi[((size_t)b*DI + n)*LSEQ + m] = v;
        else        z [((size_t)b*DI + (n - DI))*LSEQ + m] = v;
    }
};
struct EpiDbc { // dbcT (48, b*l)
    float* dbc;
    __device__ void operator()(int b, int m, int n, float v) const {
        dbc[(size_t)n*(NB*LSEQ) + b*LSEQ + m] = v;
    }
};
struct EpiDt {  // dt (b, d, l)
    float* dt; const float* bias;
    __device__ void operator()(int, int m, int n, float v) const {
        float x = v + bias[n];
        float sp = (x > 20.f) ? x : log1pf(__expf(x));
        int b = m >> 12, l = m & (LSEQ - 1);
        dt[((size_t)b*DI + n)*LSEQ + l] = sp;
    }
};
struct EpiOut {
    const float* xc; float* xr;
    __device__ void operator()(int b, int m, int n, float v) const {
        size_t idx = ((size_t)b*DM + n)*LSEQ + m;
        xr[idx] = xc[idx] + v;
    }
};

// ---------------- skip concat copy ----------------
__global__ void copy_skip(const float* __restrict__ skip, float* __restrict__ xc) {
    int idx = blockIdx.x * blockDim.x + threadIdx.x;
    int total = NB * 128 * LSEQ;
    if (idx >= total) return;
    int b = idx / (128 * LSEQ);
    int rem = idx - b * (128 * LSEQ);
    xc[((size_t)b*DM + 128)*LSEQ + rem] = skip[idx];
}

// ---------------- depthwise causal conv1d + silu, (b,d,l) -> (b,d,l) ----------------
__global__ __launch_bounds__(256)
void conv1d_kernel(const float* __restrict__ xi, const float* __restrict__ w,
                   const float* __restrict__ bias, float* __restrict__ u)
{
    __shared__ float s[32][37];
    int b  = blockIdx.z;
    int d0 = blockIdx.y * 32;
    int l0 = blockIdx.x * 32;
    int tid = threadIdx.x;
    for (int e = tid; e < 32*36; e += 256) {
        int dd = e / 36, li = e % 36;
        int l = l0 - 3 + li;
        float v = (l >= 0 && l < LSEQ) ? xi[((size_t)b*DI + d0 + dd)*LSEQ + l] : 0.f;
        s[dd][li] = v;
    }
    __syncthreads();
    int dd = tid & 31, lg = tid >> 5;
    float w0 = w[(d0+dd)*4 + 0], w1 = w[(d0+dd)*4 + 1];
    float w2 = w[(d0+dd)*4 + 2], w3 = w[(d0+dd)*4 + 3];
    float bv = bias[d0+dd];
#pragma unroll
    for (int li = lg; li < 32; li += 8) {
        float a = s[dd][li]*w0 + s[dd][li+1]*w1 + s[dd][li+2]*w2 + s[dd][li+3]*w3 + bv;
        float sv = a / (1.f + __expf(-a));
        u[((size_t)b*DI + d0 + dd)*LSEQ + l0 + li] = sv;
    }
}

// ================= chunked selective scan =================
// layout: warp handles 2 channels (16 lanes = 16 states each); gch = b*512+d
__global__ __launch_bounds__(128)
void scan_pass1(const float* __restrict__ dt, const float* __restrict__ u,
                const float* __restrict__ dbc, const float* __restrict__ A_log,
                float* __restrict__ S, float* __restrict__ sd)
{
    int lane = threadIdx.x & 31;
    int n    = lane & 15;
    int half = lane >> 4;
    int warp = threadIdx.x >> 5;
    int gch  = blockIdx.y * 8 + warp * 2 + half;
    int c    = blockIdx.x;
    int b = gch >> 9, d = gch & (DI - 1);

    float A = -__expf(A_log[d*DS + n]);
    const float* dtp = dt  + (size_t)gch*LSEQ + c*CT;
    const float* up  = u   + (size_t)gch*LSEQ + c*CT;
    const float* bp  = dbc + (size_t)(16 + n)*(NB*LSEQ) + b*LSEQ + c*CT;

    float h = 0.f, sda = 0.f;
#pragma unroll 8
    for (int l = 0; l < CT; ++l) {
        float dtv = dtp[l], uv = up[l], bn = bp[l];
        float dA = __expf(dtv * A);
        h = dA * h + (dtv * uv) * bn;
        sda += dtv;
    }
    S[((size_t)gch*NCH + c)*DS + n] = h;
    if (n == 0) sd[(size_t)gch*NCH + c] = sda;
}

__global__ __launch_bounds__(128)
void scan_pass2(const float* __restrict__ S, const float* __restrict__ sd,
                const float* __restrict__ A_log, float* __restrict__ hs)
{
    int lane = threadIdx.x & 31;
    int n    = lane & 15;
    int half = lane >> 4;
    int warp = threadIdx.x >> 5;
    int gch  = blockIdx.x * 8 + warp * 2 + half;
    int d = gch & (DI - 1);
    float A = -__expf(A_log[d*DS + n]);
    float h = 0.f;
    for (int c = 0; c < NCH; ++c) {
        size_t idx = ((size_t)gch*NCH + c)*DS + n;
        hs[idx] = h;
        float P = __expf(A * sd[(size_t)gch*NCH + c]);
        h = P * h + S[idx];
    }
}

__global__ __launch_bounds__(128)
void scan_pass3(const float* __restrict__ dt, const float* __restrict__ u,
                const float* __restrict__ dbc, const float* __restrict__ z,
                const float* __restrict__ A_log, const float* __restrict__ Dp,
                const float* __restrict__ hs, float* __restrict__ y)
{
    int lane = threadIdx.x & 31;
    int n    = lane & 15;
    int half = lane >> 4;
    int warp = threadIdx.x >> 5;
    int gch  = blockIdx.y * 8 + warp * 2 + half;
    int c    = blockIdx.x;
    int b = gch >> 9, d = gch & (DI - 1);

    float A  = -__expf(A_log[d*DS + n]);
    float Dv = Dp[d];
    const float* dtp = dt  + (size_t)gch*LSEQ + c*CT;
    const float* up  = u   + (size_t)gch*LSEQ + c*CT;
    const float* zp  = z   + (size_t)gch*LSEQ + c*CT;
    const float* bp  = dbc + (size_t)(16 + n)*(NB*LSEQ) + b*LSEQ + c*CT;
    const float* cp  = dbc + (size_t)(32 + n)*(NB*LSEQ) + b*LSEQ + c*CT;
    float*       yp  = y   + (size_t)gch*LSEQ + c*CT;

    float h = hs[((size_t)gch*NCH + c)*DS + n];
#pragma unroll 4
    for (int l = 0; l < CT; ++l) {
        float dtv = dtp[l], uv = up[l];
        float bn = bp[l], cn = cp[l];
        float dA = __expf(dtv * A);
        h = dA * h + (dtv * uv) * bn;
        float yv = h * cn;
        yv += __shfl_xor_sync(0xffffffffu, yv, 1);
        yv += __shfl_xor_sync(0xffffffffu, yv, 2);
        yv += __shfl_xor_sync(0xffffffffu, yv, 4);
        yv += __shfl_xor_sync(0xffffffffu, yv, 8);
        if (n == 0) {
            float out = yv + uv * Dv;
            float zv = zp[l];
            float sg = zv / (1.f + __expf(-zv));
            yp[l] = out * sg;
        }
    }
}

// ---------------- 3x3 conv (128 out, 256 in, pad 1), smem tiled ----------------
__global__ __launch_bounds__(256)
void conv3_kernel(const float* __restrict__ xr, const float* __restrict__ W,
                  const float* __restrict__ bias, float* __restrict__ y2)
{
    __shared__ float in_s[16][18][19];
    __shared__ float w_s[16][16][9];
    int b  = blockIdx.z;
    int o0 = blockIdx.y * 16;
    int pt = blockIdx.x;            // 16 tiles of 16x16 pixels
    int h0 = (pt >> 2) * 16;
    int w0 = (pt & 3) * 16;
    int tid = threadIdx.x;
    int wo  = tid & 63;
    int og  = tid >> 6;             // 0..3, 4 output channels each
    int prow  = wo >> 2;            // 0..15
    int pcol0 = (wo & 3) << 2;      // 0,4,8,12

    float acc[4][4];
#pragma unroll
    for (int i = 0; i < 4; i++)
#pragma unroll
        for (int j = 0; j < 4; j++) acc[i][j] = 0.f;

    const float* xrb = xr + (size_t)b * DM * LSEQ;
    for (int c0 = 0; c0 < 256; c0 += 16) {
        for (int e = tid; e < 16*18*18; e += 256) {
            int c = e / 324, r = (e % 324) / 18, cc = e % 18;
            int h = h0 + r - 1, w = w0 + cc - 1;
            float v = 0.f;
            if (h >= 0 && h < 64 && w >= 0 && w < 64)
                v = xrb[(size_t)(c0 + c)*LSEQ + h*64 + w];
            in_s[c][r][cc] = v;
        }
        for (int e = tid; e < 16*16*9; e += 256) {
            int o = e / 144, rest = e % 144, c = rest / 9, t = rest % 9;
            w_s[o][c][t] = W[(size_t)(o0 + o)*2304 + (c0 + c)*9 + t];
        }
        __syncthreads();
#pragma unroll 1
        for (int c = 0; c < 16; ++c) {
#pragma unroll
            for (int t = 0; t < 9; ++t) {
                int di = t / 3, dj = t % 3;
                float iv[4];
#pragma unroll
                for (int j = 0; j < 4; ++j) iv[j] = in_s[c][prow + di][pcol0 + dj + j];
#pragma unroll
                for (int oi = 0; oi < 4; ++oi) {
                    float wv = w_s[og*4 + oi][c][t];
#pragma unroll
                    for (int j = 0; j < 4; ++j) acc[oi][j] += wv * iv[j];
                }
            }
        }
        __syncthreads();
    }
#pragma unroll
    for (int oi = 0; oi < 4; ++oi) {
        int o = o0 + og*4 + oi;
        float bv = bias[o];
#pragma unroll
        for (int j = 0; j < 4; ++j)
            y2[((size_t)b*128 + o)*LSEQ + (h0 + prow)*64 + (w0 + pcol0 + j)] = acc[oi][j] + bv;
    }
}

// ---------------- batchnorm stats + apply + gelu ----------------
__global__ void bn_stats(const float* __restrict__ y2, float* __restrict__ mv) {
    int o = blockIdx.x;
    float s = 0.f, s2 = 0.f;
    for (int i = threadIdx.x; i < NB*LSEQ; i += 256) {
        int b = i >> 12, l = i & (LSEQ - 1);
        float v = y2[((size_t)b*128 + o)*LSEQ + l];
        s += v; s2 += v*v;
    }
    __shared__ float sh0[256], sh1[256];
    sh0[threadIdx.x] = s; sh1[threadIdx.x] = s2;
    __syncthreads();
    for (int st = 128; st > 0; st >>= 1) {
        if (threadIdx.x < st) {
            sh0[threadIdx.x] += sh0[threadIdx.x + st];
            sh1[threadIdx.x] += sh1[threadIdx.x + st];
        }
        __syncthreads();
    }
    if (threadIdx.x == 0) {
        float inv = 1.f / (NB * LSEQ);
        float mu = sh0[0] * inv;
        float var = sh1[0] * inv - mu * mu;
        mv[o] = mu; mv[128 + o] = var;
    }
}

__global__ void bn_apply(const float* __restrict__ y2, const float* __restrict__ mv,
                         const float* __restrict__ gamma, const float* __restrict__ beta,
                         float* __restrict__ out)
{
    int idx = blockIdx.x * blockDim.x + threadIdx.x;
    if (idx >= NB*128*LSEQ) return;
    int o = (idx >> 12) & 127;
    float mu = mv[o], var = mv[128 + o];
    float v = (y2[idx] - mu) * rsqrtf(var + 1e-5f) * gamma[o] + beta[o];
    out[idx] = 0.5f * v * (1.f + erff(v * 0.70710678118654752440f));
}

// ---------------- launch ----------------
extern "C" void kernel_launch(void* const* d_in, const int* in_sizes, int n_in,
                              void* d_out, int out_size)
{
    const float* x        = (const float*)d_in[0];
    const float* skip     = (const float*)d_in[1];
    const float* up_w     = (const float*)d_in[2];
    const float* up_b     = (const float*)d_in[3];
    const float* in_proj  = (const float*)d_in[4];
    const float* c1w      = (const float*)d_in[5];
    const float* c1b      = (const float*)d_in[6];
    const float* xproj    = (const float*)d_in[7];
    const float* dtw      = (const float*)d_in[8];
    const float* dtb      = (const float*)d_in[9];
    const float* A_log    = (const float*)d_in[10];
    const float* Dp       = (const float*)d_in[11];
    const float* outw     = (const float*)d_in[12];
    const float* cw       = (const float*)d_in[13];
    const float* cb       = (const float*)d_in[14];
    const float* bng      = (const float*)d_in[15];
    const float* bnb      = (const float*)d_in[16];
    float* out = (float*)d_out;

    float *xc, *xi, *z, *u, *dbc, *dtv, *y, *xr, *y2, *mv, *S, *hs, *sd;
    cudaGetSymbolAddress((void**)&xc,  g_xc);
    cudaGetSymbolAddress((void**)&xi,  g_xi);
    cudaGetSymbolAddress((void**)&z,   g_z);
    cudaGetSymbolAddress((void**)&u,   g_u);
    cudaGetSymbolAddress((void**)&dbc, g_dbc);
    cudaGetSymbolAddress((void**)&dtv, g_dt);
    cudaGetSymbolAddress((void**)&y,   g_y);
    cudaGetSymbolAddress((void**)&xr,  g_xr);
    cudaGetSymbolAddress((void**)&y2,  g_y2);
    cudaGetSymbolAddress((void**)&mv,  g_mv);
    cudaGetSymbolAddress((void**)&S,   g_S);
    cudaGetSymbolAddress((void**)&hs,  g_hs);
    cudaGetSymbolAddress((void**)&sd,  g_sd);

    // 1) upsample as GEMM: C[512, 1024] = up_w^T(512x256) * x[b](256x1024)
    gemm128<false, EpiUp><<<dim3(8, 4, NB), 256>>>(
        up_w, 512, 0, x, 1024, (long)256*1024, 512, 1024, 256, EpiUp{xc, up_b});

    // 2) skip concat
    copy_skip<<<(NB*128*LSEQ + 255)/256, 256>>>(skip, xc);

    // 3) in_proj GEMM: per batch C[4096, 1024] = xc^T(l,c) * in_proj^T
    gemm128<true, EpiXZ><<<dim3(8, 32, NB), 256>>>(
        xc, LSEQ, (long)DM*LSEQ, in_proj, DM, 0, LSEQ, 2*DI, DM, EpiXZ{xi, z});

    // 4) depthwise conv1d + silu (keeps (b,d,l) layout)
    conv1d_kernel<<<dim3(LSEQ/32, DI/32, NB), 256>>>(xi, c1w, c1b, u);

    // 5) x_proj GEMM: per batch C[4096, 48] = u^T(l,d) * xproj^T  -> dbcT (48, b*l)
    gemm_k<true, true, EpiDbc><<<dim3(1, 64, NB), 256>>>(
        u, LSEQ, (long)DI*LSEQ, xproj, DI, 0, LSEQ, 48, DI, EpiDbc{dbc});

    // 6) dt GEMM + softplus: C[8192, 512] = dbcT[:16]^T * dtw^T -> dt (b,d,l)
    gemm_k<true, true, EpiDt><<<dim3(8, 128, 1), 256>>>(
        dbc, NB*LSEQ, 0, dtw, DS, 0, NB*LSEQ, DI, DS, EpiDt{dtv, dtb});

    // 7) chunked selective scan
    scan_pass1<<<dim3(NCH, NB*DI/8), 128>>>(dtv, u, dbc, A_log, S, sd);
    scan_pass2<<<NB*DI/8, 128>>>(S, sd, A_log, hs);
    scan_pass3<<<dim3(NCH, NB*DI/8), 128>>>(dtv, u, dbc, z, A_log, Dp, hs, y);

    // 8) out_proj GEMM + residual into xr
    gemm128<true, EpiOut><<<dim3(2, 32, NB), 256>>>(
        y, LSEQ, (long)DI*LSEQ, outw, DI, 0, LSEQ, DM, DI, EpiOut{xc, xr});

    // 9) 3x3 conv (256 blocks)
    conv3_kernel<<<dim3(16, 8, NB), 256>>>(xr, cw, cb, y2);

    // 10) batchnorm stats
    bn_stats<<<128, 256>>>(y2, mv);

    // 11) batchnorm apply + gelu
    bn_apply<<<(NB*128*LSEQ + 255)/256, 256>>>(y2, mv, bng, bnb, out);
}

// round 4
// speedup vs baseline: 3.4718x; 1.0017x over previous
#include <cuda_runtime.h>
#include <math.h>
#include <stdint.h>

#define LSEQ 4096
#define DM   256
#define DI   512
#define DS   16
#define NB   2
#define NCH  64   // scan chunks
#define CT   64   // chunk length

// ---------------- scratch (device globals; no runtime alloc allowed) ----------------
__device__ float g_xc [NB*DM*LSEQ];    // (b, c=256, l)  concat of up + skip
__device__ float g_xi [NB*DI*LSEQ];    // (b, d, l)  pre-conv x branch
__device__ float g_z  [NB*DI*LSEQ];    // (b, d, l)  gate branch (pre-silu)
__device__ float g_u  [NB*DI*LSEQ];    // (b, d, l)  post conv1d + silu
__device__ float g_dbc[48*NB*LSEQ];    // (j=48, b*l) transposed [dt_rank | B | C]
__device__ float g_dt [NB*DI*LSEQ];    // (b, d, l)  softplus(dt)
__device__ float g_y  [NB*DI*LSEQ];    // (b, d, l)  scan output * silu(z)
__device__ float g_xr [NB*DM*LSEQ];    // (b, c, l)  xc + mamba out
__device__ float g_y2 [NB*128*LSEQ];   // (b, o, l)  conv3x3 out (pre-BN)
__device__ float g_mv [256];           // mean[128], var[128]
__device__ float g_S  [NB*DI*NCH*DS];  // per-chunk local end state
__device__ float g_hs [NB*DI*NCH*DS];  // per-chunk start state
__device__ float g_sd [NB*DI*NCH];     // per-chunk sum(dt)

// ================= fast 128x128x8 double-buffered fp32 GEMM =================
// C[m,n] = sum_k A[m,k]*B[k,n];  A is always k-major: A[m,k] = A[k*lda + m]
// TB: B[k,n] = B[n*ldb + k]  else B[k*ldb + n]
// Requires M%128==0, N%128==0, K%8==0.
template<bool TB, class Epi>
__global__ __launch_bounds__(256)
void gemm128(const float* __restrict__ A, int lda, long sA,
             const float* __restrict__ B, int ldb, long sB,
             int M, int N, int K, Epi epi)
{
    __shared__ float As[2][8][128];
    __shared__ float Bs[2][8][128];
    const int tid = threadIdx.x;
    const int bz  = blockIdx.z;
    const float* Ab = A + (size_t)bz * sA;
    const float* Bb = B + (size_t)bz * sB;
    const int m0 = blockIdx.y * 128;
    const int n0 = blockIdx.x * 128;
    const int tx = tid & 15, ty = tid >> 4;

    // A load coords: row k (8), col m (128)
    const int ak = tid >> 5;
    const int am = (tid & 31) << 2;
    // B load coords (TB=true): n (128), kq in {0,4}
    const int bn_ = tid >> 1;
    const int bkq = (tid & 1) << 2;

    float acc[8][8];
#pragma unroll
    for (int i = 0; i < 8; i++)
#pragma unroll
        for (int j = 0; j < 8; j++) acc[i][j] = 0.f;

    const int nt = K >> 3;

    // prologue: load tile 0 straight into smem buffer 0
    {
        float4 va = *reinterpret_cast<const float4*>(Ab + (size_t)ak*lda + m0 + am);
        *reinterpret_cast<float4*>(&As[0][ak][am]) = va;
        if (TB) {
            float4 vb = *reinterpret_cast<const float4*>(Bb + (size_t)(n0 + bn_)*ldb + bkq);
            Bs[0][bkq+0][bn_] = vb.x; Bs[0][bkq+1][bn_] = vb.y;
            Bs[0][bkq+2][bn_] = vb.z; Bs[0][bkq+3][bn_] = vb.w;
        } else {
            float4 vb = *reinterpret_cast<const float4*>(Bb + (size_t)ak*ldb + n0 + am);
            *reinterpret_cast<float4*>(&Bs[0][ak][am]) = vb;
        }
    }
    __syncthreads();

    int buf = 0;
    for (int kt = 0; kt < nt; ++kt) {
        float4 pa, pb;
        const bool has = (kt + 1 < nt);
        if (has) {
            int k0 = (kt + 1) << 3;
            pa = *reinterpret_cast<const float4*>(Ab + (size_t)(k0 + ak)*lda + m0 + am);
            if (TB)
                pb = *reinterpret_cast<const float4*>(Bb + (size_t)(n0 + bn_)*ldb + k0 + bkq);
            else
                pb = *reinterpret_cast<const float4*>(Bb + (size_t)(k0 + ak)*ldb + n0 + am);
        }
#pragma unroll
        for (int kk = 0; kk < 8; ++kk) {
            float a[8], b[8];
            *reinterpret_cast<float4*>(&a[0]) = *reinterpret_cast<const float4*>(&As[buf][kk][ty << 2]);
            *reinterpret_cast<float4*>(&a[4]) = *reinterpret_cast<const float4*>(&As[buf][kk][64 + (ty << 2)]);
            *reinterpret_cast<float4*>(&b[0]) = *reinterpret_cast<const float4*>(&Bs[buf][kk][tx << 2]);
            *reinterpret_cast<float4*>(&b[4]) = *reinterpret_cast<const float4*>(&Bs[buf][kk][64 + (tx << 2)]);
#pragma unroll
            for (int i = 0; i < 8; i++)
#pragma unroll
                for (int j = 0; j < 8; j++) acc[i][j] += a[i] * b[j];
        }
        if (has) {
            int nb = buf ^ 1;
            *reinterpret_cast<float4*>(&As[nb][ak][am]) = pa;
            if (TB) {
                Bs[nb][bkq+0][bn_] = pb.x; Bs[nb][bkq+1][bn_] = pb.y;
                Bs[nb][bkq+2][bn_] = pb.z; Bs[nb][bkq+3][bn_] = pb.w;
            } else {
                *reinterpret_cast<float4*>(&Bs[nb][ak][am]) = pb;
            }
            __syncthreads();
            buf = nb;
        }
    }

#pragma unroll
    for (int i = 0; i < 8; i++) {
        int mi = m0 + ((i < 4) ? (ty << 2) + i : 64 + (ty << 2) + (i - 4));
#pragma unroll
        for (int j = 0; j < 8; j++) {
            int ni = n0 + ((j < 4) ? (tx << 2) + j : 64 + (tx << 2) + (j - 4));
            epi(bz, mi, ni, acc[i][j]);
        }
    }
}

// ================= small generic 64x64x16 GEMM (for skinny shapes) =================
template<bool TA, bool TB, class Epi>
__global__ __launch_bounds__(256)
void gemm_k(const float* __restrict__ A, int lda, long sA,
            const float* __restrict__ B, int ldb, long sB,
            int M, int N, int K, Epi epi)
{
    __shared__ float As[16][68];
    __shared__ float Bs[16][68];
    const int tid = threadIdx.x;
    const int bz  = blockIdx.z;
    const float* Ab = A + (size_t)bz * sA;
    const float* Bb = B + (size_t)bz * sB;
    const int m0 = blockIdx.y * 64;
    const int n0 = blockIdx.x * 64;
    const int tx = tid & 15, ty = tid >> 4;

    float acc[4][4];
#pragma unroll
    for (int i = 0; i < 4; i++)
#pragma unroll
        for (int j = 0; j < 4; j++) acc[i][j] = 0.f;

    for (int k0 = 0; k0 < K; k0 += 16) {
        if (TA) {
            int k  = tid >> 4;
            int mq = (tid & 15) << 2;
            float4 v = *reinterpret_cast<const float4*>(Ab + (size_t)(k0 + k)*lda + m0 + mq);
            *reinterpret_cast<float4*>(&As[k][mq]) = v;
        } else {
            int m  = tid >> 2;
            int kq = (tid & 3) << 2;
            float4 v = *reinterpret_cast<const float4*>(Ab + (size_t)(m0 + m)*lda + k0 + kq);
            As[kq+0][m] = v.x; As[kq+1][m] = v.y; As[kq+2][m] = v.z; As[kq+3][m] = v.w;
        }
        if (TB) {
            int nn = tid >> 2;
            int kq = (tid & 3) << 2;
            float4 v = make_float4(0.f,0.f,0.f,0.f);
            if (n0 + nn < N)
                v = *reinterpret_cast<const float4*>(Bb + (size_t)(n0 + nn)*ldb + k0 + kq);
            Bs[kq+0][nn] = v.x; Bs[kq+1][nn] = v.y; Bs[kq+2][nn] = v.z; Bs[kq+3][nn] = v.w;
        } else {
            int k  = tid >> 4;
            int nq = (tid & 15) << 2;
            float4 v = *reinterpret_cast<const float4*>(Bb + (size_t)(k0 + k)*ldb + n0 + nq);
            *reinterpret_cast<float4*>(&Bs[k][nq]) = v;
        }
        __syncthreads();
#pragma unroll
        for (int kk = 0; kk < 16; ++kk) {
            float4 a4 = *reinterpret_cast<const float4*>(&As[kk][ty << 2]);
            float4 b4 = *reinterpret_cast<const float4*>(&Bs[kk][tx << 2]);
            float a[4] = {a4.x, a4.y, a4.z, a4.w};
            float b[4] = {b4.x, b4.y, b4.z, b4.w};
#pragma unroll
            for (int i = 0; i < 4; i++)
#pragma unroll
                for (int j = 0; j < 4; j++) acc[i][j] += a[i] * b[j];
        }
        __syncthreads();
    }
#pragma unroll
    for (int i = 0; i < 4; i++) {
        int mi = m0 + (ty << 2) + i;
#pragma unroll
        for (int j = 0; j < 4; j++) {
            int ni = n0 + (tx << 2) + j;
            if (mi < M && ni < N) epi(bz, mi, ni, acc[i][j]);
        }
    }
}

// ---------------- epilogues ----------------
struct EpiUp {
    float* xc; const float* up_b;
    __device__ void operator()(int b, int m, int n, float v) const {
        int o = m >> 2, i = (m >> 1) & 1, j = m & 1;
        int h = n >> 5, w = n & 31;
        xc[((size_t)b*DM + o)*LSEQ + (2*h + i)*64 + (2*w + j)] = v + up_b[o];
    }
};
struct EpiXZ {  // xi, z both (b, d, l)
    float* xi; float* z;
    __device__ void operator()(int b, int m, int n, float v) const {
        if (n < DI) xi[((size_t)b*DI + n)*LSEQ + m] = v;
        else        z [((size_t)b*DI + (n - DI))*LSEQ + m] = v;
    }
};
struct EpiDbc { // dbcT (48, b*l)
    float* dbc;
    __device__ void operator()(int b, int m, int n, float v) const {
        dbc[(size_t)n*(NB*LSEQ) + b*LSEQ + m] = v;
    }
};
struct EpiDt {  // dt (b, d, l)
    float* dt; const float* bias;
    __device__ void operator()(int, int m, int n, float v) const {
        float x = v + bias[n];
        float sp = (x > 20.f) ? x : log1pf(__expf(x));
        int b = m >> 12, l = m & (LSEQ - 1);
        dt[((size_t)b*DI + n)*LSEQ + l] = sp;
    }
};
struct EpiOut {
    const float* xc; float* xr;
    __device__ void operator()(int b, int m, int n, float v) const {
        size_t idx = ((size_t)b*DM + n)*LSEQ + m;
        xr[idx] = xc[idx] + v;
    }
};

// ---------------- skip concat copy ----------------
__global__ void copy_skip(const float* __restrict__ skip, float* __restrict__ xc) {
    int idx = blockIdx.x * blockDim.x + threadIdx.x;
    int total = NB * 128 * LSEQ;
    if (idx >= total) return;
    int b = idx / (128 * LSEQ);
    int rem = idx - b * (128 * LSEQ);
    xc[((size_t)b*DM + 128)*LSEQ + rem] = skip[idx];
}

// ---------------- depthwise causal conv1d + silu, (b,d,l) -> (b,d,l) ----------------
__global__ __launch_bounds__(256)
void conv1d_kernel(const float* __restrict__ xi, const float* __restrict__ w,
                   const float* __restrict__ bias, float* __restrict__ u)
{
    __shared__ float s[32][37];
    int b  = blockIdx.z;
    int d0 = blockIdx.y * 32;
    int l0 = blockIdx.x * 32;
    int tid = threadIdx.x;
    for (int e = tid; e < 32*36; e += 256) {
        int dd = e / 36, li = e % 36;
        int l = l0 - 3 + li;
        float v = (l >= 0 && l < LSEQ) ? xi[((size_t)b*DI + d0 + dd)*LSEQ + l] : 0.f;
        s[dd][li] = v;
    }
    __syncthreads();
    int dd = tid & 31, lg = tid >> 5;
    float w0 = w[(d0+dd)*4 + 0], w1 = w[(d0+dd)*4 + 1];
    float w2 = w[(d0+dd)*4 + 2], w3 = w[(d0+dd)*4 + 3];
    float bv = bias[d0+dd];
#pragma unroll
    for (int li = lg; li < 32; li += 8) {
        float a = s[dd][li]*w0 + s[dd][li+1]*w1 + s[dd][li+2]*w2 + s[dd][li+3]*w3 + bv;
        float sv = a / (1.f + __expf(-a));
        u[((size_t)b*DI + d0 + dd)*LSEQ + l0 + li] = sv;
    }
}

// ================= chunked selective scan =================
// layout: warp handles 2 channels (16 lanes = 16 states each); gch = b*512+d
__global__ __launch_bounds__(128)
void scan_pass1(const float* __restrict__ dt, const float* __restrict__ u,
                const float* __restrict__ dbc, const float* __restrict__ A_log,
                float* __restrict__ S, float* __restrict__ sd)
{
    int lane = threadIdx.x & 31;
    int n    = lane & 15;
    int half = lane >> 4;
    int warp = threadIdx.x >> 5;
    int gch  = blockIdx.y * 8 + warp * 2 + half;
    int c    = blockIdx.x;
    int b = gch >> 9, d = gch & (DI - 1);

    float A = -__expf(A_log[d*DS + n]);
    const float* dtp = dt  + (size_t)gch*LSEQ + c*CT;
    const float* up  = u   + (size_t)gch*LSEQ + c*CT;
    const float* bp  = dbc + (size_t)(16 + n)*(NB*LSEQ) + b*LSEQ + c*CT;

    float h = 0.f, sda = 0.f;
#pragma unroll 8
    for (int l = 0; l < CT; ++l) {
        float dtv = dtp[l], uv = up[l], bn = bp[l];
        float dA = __expf(dtv * A);
        h = dA * h + (dtv * uv) * bn;
        sda += dtv;
    }
    S[((size_t)gch*NCH + c)*DS + n] = h;
    if (n == 0) sd[(size_t)gch*NCH + c] = sda;
}

__global__ __launch_bounds__(128)
void scan_pass2(const float* __restrict__ S, const float* __restrict__ sd,
                const float* __restrict__ A_log, float* __restrict__ hs)
{
    int lane = threadIdx.x & 31;
    int n    = lane & 15;
    int half = lane >> 4;
    int warp = threadIdx.x >> 5;
    int gch  = blockIdx.x * 8 + warp * 2 + half;
    int d = gch & (DI - 1);
    float A = -__expf(A_log[d*DS + n]);
    float h = 0.f;
    for (int c = 0; c < NCH; ++c) {
        size_t idx = ((size_t)gch*NCH + c)*DS + n;
        hs[idx] = h;
        float P = __expf(A * sd[(size_t)gch*NCH + c]);
        h = P * h + S[idx];
    }
}

__global__ __launch_bounds__(128)
void scan_pass3(const float* __restrict__ dt, const float* __restrict__ u,
                const float* __restrict__ dbc, const float* __restrict__ z,
                const float* __restrict__ A_log, const float* __restrict__ Dp,
                const float* __restrict__ hs, float* __restrict__ y)
{
    int lane = threadIdx.x & 31;
    int n    = lane & 15;
    int half = lane >> 4;
    int warp = threadIdx.x >> 5;
    int gch  = blockIdx.y * 8 + warp * 2 + half;
    int c    = blockIdx.x;
    int b = gch >> 9, d = gch & (DI - 1);

    float A  = -__expf(A_log[d*DS + n]);
    float Dv = Dp[d];
    const float* dtp = dt  + (size_t)gch*LSEQ + c*CT;
    const float* up  = u   + (size_t)gch*LSEQ + c*CT;
    const float* zp  = z   + (size_t)gch*LSEQ + c*CT;
    const float* bp  = dbc + (size_t)(16 + n)*(NB*LSEQ) + b*LSEQ + c*CT;
    const float* cp  = dbc + (size_t)(32 + n)*(NB*LSEQ) + b*LSEQ + c*CT;
    float*       yp  = y   + (size_t)gch*LSEQ + c*CT;

    float h = hs[((size_t)gch*NCH + c)*DS + n];
#pragma unroll 4
    for (int l = 0; l < CT; ++l) {
        float dtv = dtp[l], uv = up[l];
        float bn = bp[l], cn = cp[l];
        float dA = __expf(dtv * A);
        h = dA * h + (dtv * uv) * bn;
        float yv = h * cn;
        yv += __shfl_xor_sync(0xffffffffu, yv, 1);
        yv += __shfl_xor_sync(0xffffffffu, yv, 2);
        yv += __shfl_xor_sync(0xffffffffu, yv, 4);
        yv += __shfl_xor_sync(0xffffffffu, yv, 8);
        if (n == 0) {
            float out = yv + uv * Dv;
            float zv = zp[l];
            float sg = zv / (1.f + __expf(-zv));
            yp[l] = out * sg;
        }
    }
}

// ---------------- 3x3 conv (128 out, 256 in, pad 1), smem tiled ----------------
__global__ __launch_bounds__(256)
void conv3_kernel(const float* __restrict__ xr, const float* __restrict__ W,
                  const float* __restrict__ bias, float* __restrict__ y2)
{
    __shared__ float in_s[16][18][19];
    __shared__ float w_s[16][16][9];
    int b  = blockIdx.z;
    int o0 = blockIdx.y * 16;
    int pt = blockIdx.x;            // 16 tiles of 16x16 pixels
    int h0 = (pt >> 2) * 16;
    int w0 = (pt & 3) * 16;
    int tid = threadIdx.x;
    int wo  = tid & 63;
    int og  = tid >> 6;             // 0..3, 4 output channels each
    int prow  = wo >> 2;            // 0..15
    int pcol0 = (wo & 3) << 2;      // 0,4,8,12

    float acc[4][4];
#pragma unroll
    for (int i = 0; i < 4; i++)
#pragma unroll
        for (int j = 0; j < 4; j++) acc[i][j] = 0.f;

    const float* xrb = xr + (size_t)b * DM * LSEQ;
    for (int c0 = 0; c0 < 256; c0 += 16) {
        for (int e = tid; e < 16*18*18; e += 256) {
            int c = e / 324, r = (e % 324) / 18, cc = e % 18;
            int h = h0 + r - 1, w = w0 + cc - 1;
            float v = 0.f;
            if (h >= 0 && h < 64 && w >= 0 && w < 64)
                v = xrb[(size_t)(c0 + c)*LSEQ + h*64 + w];
            in_s[c][r][cc] = v;
        }
        for (int e = tid; e < 16*16*9; e += 256) {
            int o = e / 144, rest = e % 144, c = rest / 9, t = rest % 9;
            w_s[o][c][t] = W[(size_t)(o0 + o)*2304 + (c0 + c)*9 + t];
        }
        __syncthreads();
#pragma unroll 1
        for (int c = 0; c < 16; ++c) {
#pragma unroll
            for (int t = 0; t < 9; ++t) {
                int di = t / 3, dj = t % 3;
                float iv[4];
#pragma unroll
                for (int j = 0; j < 4; ++j) iv[j] = in_s[c][prow + di][pcol0 + dj + j];
#pragma unroll
                for (int oi = 0; oi < 4; ++oi) {
                    float wv = w_s[og*4 + oi][c][t];
#pragma unroll
                    for (int j = 0; j < 4; ++j) acc[oi][j] += wv * iv[j];
                }
            }
        }
        __syncthreads();
    }
#pragma unroll
    for (int oi = 0; oi < 4; ++oi) {
        int o = o0 + og*4 + oi;
        float bv = bias[o];
#pragma unroll
        for (int j = 0; j < 4; ++j)
            y2[((size_t)b*128 + o)*LSEQ + (h0 + prow)*64 + (w0 + pcol0 + j)] = acc[oi][j] + bv;
    }
}

// ---------------- batchnorm stats + apply + gelu ----------------
__global__ void bn_stats(const float* __restrict__ y2, float* __restrict__ mv) {
    int o = blockIdx.x;
    float s = 0.f, s2 = 0.f;
    for (int i = threadIdx.x; i < NB*LSEQ; i += 256) {
        int b = i >> 12, l = i & (LSEQ - 1);
        float v = y2[((size_t)b*128 + o)*LSEQ + l];
        s += v; s2 += v*v;
    }
    __shared__ float sh0[256], sh1[256];
    sh0[threadIdx.x] = s; sh1[threadIdx.x] = s2;
    __syncthreads();
    for (int st = 128; st > 0; st >>= 1) {
        if (threadIdx.x < st) {
            sh0[threadIdx.x] += sh0[threadIdx.x + st];
            sh1[threadIdx.x] += sh1[threadIdx.x + st];
        }
        __syncthreads();
    }
    if (threadIdx.x == 0) {
        float inv = 1.f / (NB * LSEQ);
        float mu = sh0[0] * inv;
        float var = sh1[0] * inv - mu * mu;
        mv[o] = mu; mv[128 + o] = var;
    }
}

__global__ void bn_apply(const float* __restrict__ y2, const float* __restrict__ mv,
                         const float* __restrict__ gamma, const float* __restrict__ beta,
                         float* __restrict__ out)
{
    int idx = blockIdx.x * blockDim.x + threadIdx.x;
    if (idx >= NB*128*LSEQ) return;
    int o = (idx >> 12) & 127;
    float mu = mv[o], var = mv[128 + o];
    float v = (y2[idx] - mu) * rsqrtf(var + 1e-5f) * gamma[o] + beta[o];
    out[idx] = 0.5f * v * (1.f + erff(v * 0.70710678118654752440f));
}

// ---------------- launch ----------------
extern "C" void kernel_launch(void* const* d_in, const int* in_sizes, int n_in,
                              void* d_out, int out_size)
{
    const float* x        = (const float*)d_in[0];
    const float* skip     = (const float*)d_in[1];
    const float* up_w     = (const float*)d_in[2];
    const float* up_b     = (const float*)d_in[3];
    const float* in_proj  = (const float*)d_in[4];
    const float* c1w      = (const float*)d_in[5];
    const float* c1b      = (const float*)d_in[6];
    const float* xproj    = (const float*)d_in[7];
    const float* dtw      = (const float*)d_in[8];
    const float* dtb      = (const float*)d_in[9];
    const float* A_log    = (const float*)d_in[10];
    const float* Dp       = (const float*)d_in[11];
    const float* outw     = (const float*)d_in[12];
    const float* cw       = (const float*)d_in[13];
    const float* cb       = (const float*)d_in[14];
    const float* bng      = (const float*)d_in[15];
    const float* bnb      = (const float*)d_in[16];
    float* out = (float*)d_out;

    float *xc, *xi, *z, *u, *dbc, *dtv, *y, *xr, *y2, *mv, *S, *hs, *sd;
    cudaGetSymbolAddress((void**)&xc,  g_xc);
    cudaGetSymbolAddress((void**)&xi,  g_xi);
    cudaGetSymbolAddress((void**)&z,   g_z);
    cudaGetSymbolAddress((void**)&u,   g_u);
    cudaGetSymbolAddress((void**)&dbc, g_dbc);
    cudaGetSymbolAddress((void**)&dtv, g_dt);
    cudaGetSymbolAddress((void**)&y,   g_y);
    cudaGetSymbolAddress((void**)&xr,  g_xr);
    cudaGetSymbolAddress((void**)&y2,  g_y2);
    cudaGetSymbolAddress((void**)&mv,  g_mv);
    cudaGetSymbolAddress((void**)&S,   g_S);
    cudaGetSymbolAddress((void**)&hs,  g_hs);
    cudaGetSymbolAddress((void**)&sd,  g_sd);

    // 1) upsample as GEMM: C[512, 1024] = up_w^T(512x256) * x[b](256x1024)
    gemm128<false, EpiUp><<<dim3(8, 4, NB), 256>>>(
        up_w, 512, 0, x, 1024, (long)256*1024, 512, 1024, 256, EpiUp{xc, up_b});

    // 2) skip concat
    copy_skip<<<(NB*128*LSEQ + 255)/256, 256>>>(skip, xc);

    // 3) in_proj GEMM: per batch C[4096, 1024] = xc^T(l,c) * in_proj^T
    gemm128<true, EpiXZ><<<dim3(8, 32, NB), 256>>>(
        xc, LSEQ, (long)DM*LSEQ, in_proj, DM, 0, LSEQ, 2*DI, DM, EpiXZ{xi, z});

    // 4) depthwise conv1d + silu (keeps (b,d,l) layout)
    conv1d_kernel<<<dim3(LSEQ/32, DI/32, NB), 256>>>(xi, c1w, c1b, u);

    // 5) x_proj GEMM: per batch C[4096, 48] = u^T(l,d) * xproj^T  -> dbcT (48, b*l)
    gemm_k<true, true, EpiDbc><<<dim3(1, 64, NB), 256>>>(
        u, LSEQ, (long)DI*LSEQ, xproj, DI, 0, LSEQ, 48, DI, EpiDbc{dbc});

    // 6) dt GEMM + softplus: C[8192, 512] = dbcT[:16]^T * dtw^T -> dt (b,d,l)
    gemm_k<true, true, EpiDt><<<dim3(8, 128, 1), 256>>>(
        dbc, NB*LSEQ, 0, dtw, DS, 0, NB*LSEQ, DI, DS, EpiDt{dtv, dtb});

    // 7) chunked selective scan
    scan_pass1<<<dim3(NCH, NB*DI/8), 128>>>(dtv, u, dbc, A_log, S, sd);
    scan_pass2<<<NB*DI/8, 128>>>(S, sd, A_log, hs);
    scan_pass3<<<dim3(NCH, NB*DI/8), 128>>>(dtv, u, dbc, z, A_log, Dp, hs, y);

    // 8) out_proj GEMM + residual into xr
    gemm128<true, EpiOut><<<dim3(2, 32, NB), 256>>>(
        y, LSEQ, (long)DI*LSEQ, outw, DI, 0, LSEQ, DM, DI, EpiOut{xc, xr});

    // 9) 3x3 conv (256 blocks)
    conv3_kernel<<<dim3(16, 8, NB), 256>>>(xr, cw, cb, y2);

    // 10) batchnorm stats
    bn_stats<<<128, 256>>>(y2, mv);

    // 11) batchnorm apply + gelu
    bn_apply<<<(NB*128*LSEQ + 255)/256, 256>>>(y2, mv, bng, bnb, out);
}

// round 6
// speedup vs baseline: 3.4805x; 1.0025x over previous
#include <cuda_runtime.h>
#include <math.h>
#include <stdint.h>

#define LSEQ 4096
#define DM   256
#define DI   512
#define DS   16
#define NB   2
#define NCH  64   // scan chunks
#define CT   64   // chunk length

// ---------------- scratch (device globals; no runtime alloc allowed) ----------------
__device__ __align__(16) float g_xc [NB*DM*LSEQ];    // (b, c=256, l)
__device__ __align__(16) float g_xi [NB*DI*LSEQ];    // (b, d, l)
__device__ __align__(16) float g_z  [NB*DI*LSEQ];    // (b, d, l)
__device__ __align__(16) float g_u  [NB*DI*LSEQ];    // (b, d, l)
__device__ __align__(16) float g_dbc[48*NB*LSEQ];    // (j=48, b*l)
__device__ __align__(16) float g_dt [NB*DI*LSEQ];    // (b, d, l)
__device__ __align__(16) float g_y  [NB*DI*LSEQ];    // (b, d, l)
__device__ __align__(16) float g_xr [NB*DM*LSEQ];    // (b, c, l)
__device__ __align__(16) float g_y2 [NB*128*LSEQ];   // (b, o, l)
__device__ __align__(16) float g_mv [256];
__device__ __align__(16) float g_S  [NB*DI*NCH*DS];
__device__ __align__(16) float g_hs [NB*DI*NCH*DS];
__device__ __align__(16) float g_sd [NB*DI*NCH];
__device__ __align__(16) float g_wt1[256*1024];      // in_proj_w^T  (k=256, n=1024)
__device__ __align__(16) float g_wt2[512*256];       // out_proj_w^T (k=512, n=256)
__device__ __align__(16) float g_wt3[512*48 + 64];   // x_proj_w^T   (k=512, n=48) + pad

// ---------------- cp.async helpers ----------------
__device__ __forceinline__ void cp16(uint32_t dst, const float* src) {
    asm volatile("cp.async.cg.shared.global [%0], [%1], 16;\n" :: "r"(dst), "l"(src));
}
__device__ __forceinline__ void cp_commit() {
    asm volatile("cp.async.commit_group;\n");
}
__device__ __forceinline__ void cp_wait_dyn(int allow) {
    if (allow <= 0)      asm volatile("cp.async.wait_group 0;\n");
    else if (allow == 1) asm volatile("cp.async.wait_group 1;\n");
    else                 asm volatile("cp.async.wait_group 2;\n");
}

// ================= 128x128x8, 4-stage cp.async fp32 GEMM =================
// C[m,n] = sum_k A[m,k]*B[k,n]; A k-major (A[k*lda+m]), B k-major (B[k*ldb+n]).
// Requires M%128==0, N%128==0, K%8==0, K/8 >= 3.
template<class Epi>
__global__ __launch_bounds__(256, 2)
void gemm128(const float* __restrict__ A, int lda, long sA,
             const float* __restrict__ B, int ldb, long sB,
             int M, int N, int K, Epi epi)
{
    __shared__ float As[4][8][128];
    __shared__ float Bs[4][8][128];
    const int tid = threadIdx.x;
    const int bz  = blockIdx.z;
    const float* Ab = A + (size_t)bz * sA;
    const float* Bb = B + (size_t)bz * sB;
    const int m0 = blockIdx.y * 128;
    const int n0 = blockIdx.x * 128;
    const int tx = tid & 15, ty = tid >> 4;

    const int ak = tid >> 5;          // k row 0..7
    const int am = (tid & 31) << 2;   // 4-float column group

    float acc[8][8];
#pragma unroll
    for (int i = 0; i < 8; i++)
#pragma unroll
        for (int j = 0; j < 8; j++) acc[i][j] = 0.f;

    const int nt = K >> 3;

    auto ldtile = [&](int st, int k0) {
        uint32_t da = (uint32_t)__cvta_generic_to_shared(&As[st][ak][am]);
        uint32_t db = (uint32_t)__cvta_generic_to_shared(&Bs[st][ak][am]);
        cp16(da, Ab + (size_t)(k0 + ak)*lda + m0 + am);
        cp16(db, Bb + (size_t)(k0 + ak)*ldb + n0 + am);
        cp_commit();
    };

    ldtile(0, 0);
    ldtile(1, 8);
    ldtile(2, 16);

    for (int kt = 0; kt < nt; ++kt) {
        int rem = nt - 1 - kt;
        cp_wait_dyn(rem > 2 ? 2 : rem);
        __syncthreads();
        if (kt + 3 < nt) ldtile((kt + 3) & 3, (kt + 3) << 3);

        const int st = kt & 3;
#pragma unroll
        for (int kk = 0; kk < 8; ++kk) {
            float a[8], b[8];
            *reinterpret_cast<float4*>(&a[0]) = *reinterpret_cast<const float4*>(&As[st][kk][ty << 2]);
            *reinterpret_cast<float4*>(&a[4]) = *reinterpret_cast<const float4*>(&As[st][kk][64 + (ty << 2)]);
            *reinterpret_cast<float4*>(&b[0]) = *reinterpret_cast<const float4*>(&Bs[st][kk][tx << 2]);
            *reinterpret_cast<float4*>(&b[4]) = *reinterpret_cast<const float4*>(&Bs[st][kk][64 + (tx << 2)]);
#pragma unroll
            for (int i = 0; i < 8; i++)
#pragma unroll
                for (int j = 0; j < 8; j++) acc[i][j] += a[i] * b[j];
        }
    }

#pragma unroll
    for (int i = 0; i < 8; i++) {
        int mi = m0 + ((i < 4) ? (ty << 2) + i : 64 + (ty << 2) + (i - 4));
#pragma unroll
        for (int j = 0; j < 8; j++) {
            int ni = n0 + ((j < 4) ? (tx << 2) + j : 64 + (tx << 2) + (j - 4));
            epi(bz, mi, ni, acc[i][j]);
        }
    }
}

// ================= small generic 64x64x16 GEMM (x_proj: N=48) =================
template<bool TA, bool TB, class Epi>
__global__ __launch_bounds__(256)
void gemm_k(const float* __restrict__ A, int lda, long sA,
            const float* __restrict__ B, int ldb, long sB,
            int M, int N, int K, Epi epi)
{
    __shared__ float As[16][68];
    __shared__ float Bs[16][68];
    const int tid = threadIdx.x;
    const int bz  = blockIdx.z;
    const float* Ab = A + (size_t)bz * sA;
    const float* Bb = B + (size_t)bz * sB;
    const int m0 = blockIdx.y * 64;
    const int n0 = blockIdx.x * 64;
    const int tx = tid & 15, ty = tid >> 4;

    float acc[4][4];
#pragma unroll
    for (int i = 0; i < 4; i++)
#pragma unroll
        for (int j = 0; j < 4; j++) acc[i][j] = 0.f;

    for (int k0 = 0; k0 < K; k0 += 16) {
        if (TA) {
            int k  = tid >> 4;
            int mq = (tid & 15) << 2;
            float4 v = *reinterpret_cast<const float4*>(Ab + (size_t)(k0 + k)*lda + m0 + mq);
            *reinterpret_cast<float4*>(&As[k][mq]) = v;
        } else {
            int m  = tid >> 2;
            int kq = (tid & 3) << 2;
            float4 v = *reinterpret_cast<const float4*>(Ab + (size_t)(m0 + m)*lda + k0 + kq);
            As[kq+0][m] = v.x; As[kq+1][m] = v.y; As[kq+2][m] = v.z; As[kq+3][m] = v.w;
        }
        if (TB) {
            int nn = tid >> 2;
            int kq = (tid & 3) << 2;
            float4 v = make_float4(0.f,0.f,0.f,0.f);
            if (n0 + nn < N)
                v = *reinterpret_cast<const float4*>(Bb + (size_t)(n0 + nn)*ldb + k0 + kq);
            Bs[kq+0][nn] = v.x; Bs[kq+1][nn] = v.y; Bs[kq+2][nn] = v.z; Bs[kq+3][nn] = v.w;
        } else {
            int k  = tid >> 4;
            int nq = (tid & 15) << 2;
            float4 v = *reinterpret_cast<const float4*>(Bb + (size_t)(k0 + k)*ldb + n0 + nq);
            *reinterpret_cast<float4*>(&Bs[k][nq]) = v;
        }
        __syncthreads();
#pragma unroll
        for (int kk = 0; kk < 16; ++kk) {
            float4 a4 = *reinterpret_cast<const float4*>(&As[kk][ty << 2]);
            float4 b4 = *reinterpret_cast<const float4*>(&Bs[kk][tx << 2]);
            float a[4] = {a4.x, a4.y, a4.z, a4.w};
            float b[4] = {b4.x, b4.y, b4.z, b4.w};
#pragma unroll
            for (int i = 0; i < 4; i++)
#pragma unroll
                for (int j = 0; j < 4; j++) acc[i][j] += a[i] * b[j];
        }
        __syncthreads();
    }
#pragma unroll
    for (int i = 0; i < 4; i++) {
        int mi = m0 + (ty << 2) + i;
#pragma unroll
        for (int j = 0; j < 4; j++) {
            int ni = n0 + (tx << 2) + j;
            if (mi < M && ni < N) epi(bz, mi, ni, acc[i][j]);
        }
    }
}

// ---------------- weight transpose: in (R,C) -> out (C,R) ----------------
__global__ void transp(const float* __restrict__ in, float* __restrict__ out, int R, int C) {
    __shared__ float t[32][33];
    int r0 = blockIdx.y * 32, c0 = blockIdx.x * 32;
    int x = threadIdx.x, y = threadIdx.y;
    for (int i = y; i < 32; i += 8) {
        int r = r0 + i, c = c0 + x;
        t[i][x] = (r < R && c < C) ? in[(size_t)r*C + c] : 0.f;
    }
    __syncthreads();
    for (int i = y; i < 32; i += 8) {
        int c = c0 + i, r = r0 + x;
        if (c < C && r < R) out[(size_t)c*R + r] = t[x][i];
    }
}

// ---------------- epilogues ----------------
struct EpiUp {
    float* xc; const float* up_b;
    __device__ void operator()(int b, int m, int n, float v) const {
        int o = m >> 2, i = (m >> 1) & 1, j = m & 1;
        int h = n >> 5, w = n & 31;
        xc[((size_t)b*DM + o)*LSEQ + (2*h + i)*64 + (2*w + j)] = v + up_b[o];
    }
};
struct EpiXZ {
    float* xi; float* z;
    __device__ void operator()(int b, int m, int n, float v) const {
        if (n < DI) xi[((size_t)b*DI + n)*LSEQ + m] = v;
        else        z [((size_t)b*DI + (n - DI))*LSEQ + m] = v;
    }
};
struct EpiDbc {
    float* dbc;
    __device__ void operator()(int b, int m, int n, float v) const {
        dbc[(size_t)n*(NB*LSEQ) + b*LSEQ + m] = v;
    }
};
struct EpiOut {
    const float* xc; float* xr;
    __device__ void operator()(int b, int m, int n, float v) const {
        size_t idx = ((size_t)b*DM + n)*LSEQ + m;
        xr[idx] = xc[idx] + v;
    }
};

// ---------------- skip concat copy ----------------
__global__ void copy_skip(const float* __restrict__ skip, float* __restrict__ xc) {
    int idx = blockIdx.x * blockDim.x + threadIdx.x;
    int total = NB * 128 * LSEQ;
    if (idx >= total) return;
    int b = idx / (128 * LSEQ);
    int rem = idx - b * (128 * LSEQ);
    xc[((size_t)b*DM + 128)*LSEQ + rem] = skip[idx];
}

// ---------------- depthwise causal conv1d + silu (coalesced) ----------------
__global__ __launch_bounds__(256)
void conv1d_kernel(const float* __restrict__ xi, const float* __restrict__ w,
                   const float* __restrict__ bias, float* __restrict__ u)
{
    __shared__ float s[32][132];
    __shared__ float sw[32][4];
    __shared__ float sb[32];
    int b  = blockIdx.z;
    int d0 = blockIdx.y * 32;
    int l0 = blockIdx.x * 128;
    int tid = threadIdx.x;
    for (int e = tid; e < 32*132; e += 256) {
        int dd = e / 132, li = e - dd*132;
        if (li < 131) {
            int l = l0 - 3 + li;
            s[dd][li] = (l >= 0 && l < LSEQ) ? xi[((size_t)b*DI + d0 + dd)*LSEQ + l] : 0.f;
        }
    }
    if (tid < 128) sw[tid >> 2][tid & 3] = w[(d0 + (tid >> 2))*4 + (tid & 3)];
    if (tid < 32)  sb[tid] = bias[d0 + tid];
    __syncthreads();
#pragma unroll
    for (int it = 0; it < 16; ++it) {
        int idx = it*256 + tid;
        int dd = idx >> 7, li = idx & 127;
        float a = s[dd][li]*sw[dd][0] + s[dd][li+1]*sw[dd][1]
                + s[dd][li+2]*sw[dd][2] + s[dd][li+3]*sw[dd][3] + sb[dd];
        float sv = a / (1.f + __expf(-a));
        u[((size_t)b*DI + d0 + dd)*LSEQ + l0 + li] = sv;
    }
}

// ---------------- dt = softplus(dbc[:,:16] @ dtw^T + dtb), out (b,d,l) ----------------
__global__ __launch_bounds__(256)
void dt_kernel(const float* __restrict__ dbc, const float* __restrict__ dtw,
               const float* __restrict__ dtb, float* __restrict__ dt)
{
    __shared__ float swt[DI*16];   // dtw (512,16) row-major
    __shared__ float sbc[16*64];   // dbc tile: 16 rows x 64 l
    __shared__ float sbias[DI];
    int bl0 = blockIdx.x * 64;
    int tid = threadIdx.x;
    for (int i = tid; i < DI*16; i += 256) swt[i] = dtw[i];
    for (int i = tid; i < DI; i += 256) sbias[i] = dtb[i];
    for (int i = tid; i < 16*64; i += 256) {
        int r = i >> 6, li = i & 63;
        sbc[i] = dbc[(size_t)r*(NB*LSEQ) + bl0 + li];
    }
    __syncthreads();
    int b  = bl0 >> 12;
    int l0 = bl0 & (LSEQ - 1);
#pragma unroll 4
    for (int it = 0; it < 128; ++it) {
        int idx = it*256 + tid;
        int d = idx >> 6, li = idx & 63;
        float acc = sbias[d];
#pragma unroll
        for (int r = 0; r < 16; ++r) acc += swt[d*16 + r] * sbc[r*64 + li];
        float sp = (acc > 20.f) ? acc : log1pf(__expf(acc));
        dt[((size_t)b*DI + d)*LSEQ + l0 + li] = sp;
    }
}

// ================= chunked selective scan =================
__global__ __launch_bounds__(128)
void scan_pass1(const float* __restrict__ dt, const float* __restrict__ u,
                const float* __restrict__ dbc, const float* __restrict__ A_log,
                float* __restrict__ S, float* __restrict__ sd)
{
    int lane = threadIdx.x & 31;
    int n    = lane & 15;
    int half = lane >> 4;
    int warp = threadIdx.x >> 5;
    int gch  = blockIdx.y * 8 + warp * 2 + half;
    int c    = blockIdx.x;
    int b = gch >> 9, d = gch & (DI - 1);

    float A = -__expf(A_log[d*DS + n]);
    const float* dtp = dt  + (size_t)gch*LSEQ + c*CT;
    const float* up  = u   + (size_t)gch*LSEQ + c*CT;
    const float* bp  = dbc + (size_t)(16 + n)*(NB*LSEQ) + b*LSEQ + c*CT;

    float h = 0.f, sda = 0.f;
#pragma unroll 8
    for (int l = 0; l < CT; ++l) {
        float dtv = dtp[l], uv = up[l], bn = bp[l];
        float dA = __expf(dtv * A);
        h = dA * h + (dtv * uv) * bn;
        sda += dtv;
    }
    S[((size_t)gch*NCH + c)*DS + n] = h;
    if (n == 0) sd[(size_t)gch*NCH + c] = sda;
}

__global__ __launch_bounds__(128)
void scan_pass2(const float* __restrict__ S, const float* __restrict__ sd,
                const float* __restrict__ A_log, float* __restrict__ hs)
{
    int lane = threadIdx.x & 31;
    int n    = lane & 15;
    int half = lane >> 4;
    int warp = threadIdx.x >> 5;
    int gch  = blockIdx.x * 8 + warp * 2 + half;
    int d = gch & (DI - 1);
    float A = -__expf(A_log[d*DS + n]);
    float h = 0.f;
    for (int c = 0; c < NCH; ++c) {
        size_t idx = ((size_t)gch*NCH + c)*DS + n;
        hs[idx] = h;
        float P = __expf(A * sd[(size_t)gch*NCH + c]);
        h = P * h + S[idx];
    }
}

__global__ __launch_bounds__(128)
void scan_pass3(const float* __restrict__ dt, const float* __restrict__ u,
                const float* __restrict__ dbc, const float* __restrict__ z,
                const float* __restrict__ A_log, const float* __restrict__ Dp,
                const float* __restrict__ hs, float* __restrict__ y)
{
    int lane = threadIdx.x & 31;
    int n    = lane & 15;
    int half = lane >> 4;
    int warp = threadIdx.x >> 5;
    int gch  = blockIdx.y * 8 + warp * 2 + half;
    int c    = blockIdx.x;
    int b = gch >> 9, d = gch & (DI - 1);

    float A  = -__expf(A_log[d*DS + n]);
    float Dv = Dp[d];
    const float* dtp = dt  + (size_t)gch*LSEQ + c*CT;
    const float* up  = u   + (size_t)gch*LSEQ + c*CT;
    const float* zp  = z   + (size_t)gch*LSEQ + c*CT;
    const float* bp  = dbc + (size_t)(16 + n)*(NB*LSEQ) + b*LSEQ + c*CT;
    const float* cp  = dbc + (size_t)(32 + n)*(NB*LSEQ) + b*LSEQ + c*CT;
    float*       yp  = y   + (size_t)gch*LSEQ + c*CT;

    float h = hs[((size_t)gch*NCH + c)*DS + n];
#pragma unroll 4
    for (int l = 0; l < CT; ++l) {
        float dtv = dtp[l], uv = up[l];
        float bn = bp[l], cn = cp[l];
        float dA = __expf(dtv * A);
        h = dA * h + (dtv * uv) * bn;
        float yv = h * cn;
        yv += __shfl_xor_sync(0xffffffffu, yv, 1);
        yv += __shfl_xor_sync(0xffffffffu, yv, 2);
        yv += __shfl_xor_sync(0xffffffffu, yv, 4);
        yv += __shfl_xor_sync(0xffffffffu, yv, 8);
        if (n == 0) {
            float out = yv + uv * Dv;
            float zv = zp[l];
            float sg = zv / (1.f + __expf(-zv));
            yp[l] = out * sg;
        }
    }
}

// ---------------- 3x3 conv (128 out, 256 in, pad 1), smem tiled ----------------
__global__ __launch_bounds__(256)
void conv3_kernel(const float* __restrict__ xr, const float* __restrict__ W,
                  const float* __restrict__ bias, float* __restrict__ y2)
{
    __shared__ float in_s[16][18][19];
    __shared__ float w_s[16][16][9];
    int b  = blockIdx.z;
    int o0 = blockIdx.y * 16;
    int pt = blockIdx.x;
    int h0 = (pt >> 2) * 16;
    int w0 = (pt & 3) * 16;
    int tid = threadIdx.x;
    int wo  = tid & 63;
    int og  = tid >> 6;
    int prow  = wo >> 2;
    int pcol0 = (wo & 3) << 2;

    float acc[4][4];
#pragma unroll
    for (int i = 0; i < 4; i++)
#pragma unroll
        for (int j = 0; j < 4; j++) acc[i][j] = 0.f;

    const float* xrb = xr + (size_t)b * DM * LSEQ;
    for (int c0 = 0; c0 < 256; c0 += 16) {
        for (int e = tid; e < 16*18*18; e += 256) {
            int c = e / 324, r = (e % 324) / 18, cc = e % 18;
            int h = h0 + r - 1, w = w0 + cc - 1;
            float v = 0.f;
            if (h >= 0 && h < 64 && w >= 0 && w < 64)
                v = xrb[(size_t)(c0 + c)*LSEQ + h*64 + w];
            in_s[c][r][cc] = v;
        }
        for (int e = tid; e < 16*16*9; e += 256) {
            int o = e / 144, rest = e % 144, c = rest / 9, t = rest % 9;
            w_s[o][c][t] = W[(size_t)(o0 + o)*2304 + (c0 + c)*9 + t];
        }
        __syncthreads();
#pragma unroll 1
        for (int c = 0; c < 16; ++c) {
#pragma unroll
            for (int t = 0; t < 9; ++t) {
                int di = t / 3, dj = t % 3;
                float iv[4];
#pragma unroll
                for (int j = 0; j < 4; ++j) iv[j] = in_s[c][prow + di][pcol0 + dj + j];
#pragma unroll
                for (int oi = 0; oi < 4; ++oi) {
                    float wv = w_s[og*4 + oi][c][t];
#pragma unroll
                    for (int j = 0; j < 4; ++j) acc[oi][j] += wv * iv[j];
                }
            }
        }
        __syncthreads();
    }
#pragma unroll
    for (int oi = 0; oi < 4; ++oi) {
        int o = o0 + og*4 + oi;
        float bv = bias[o];
#pragma unroll
        for (int j = 0; j < 4; ++j)
            y2[((size_t)b*128 + o)*LSEQ + (h0 + prow)*64 + (w0 + pcol0 + j)] = acc[oi][j] + bv;
    }
}

// ---------------- batchnorm stats + apply + gelu ----------------
__global__ void bn_stats(const float* __restrict__ y2, float* __restrict__ mv) {
    int o = blockIdx.x;
    float s = 0.f, s2 = 0.f;
    for (int i = threadIdx.x; i < NB*LSEQ; i += 256) {
        int b = i >> 12, l = i & (LSEQ - 1);
        float v = y2[((size_t)b*128 + o)*LSEQ + l];
        s += v; s2 += v*v;
    }
    __shared__ float sh0[256], sh1[256];
    sh0[threadIdx.x] = s; sh1[threadIdx.x] = s2;
    __syncthreads();
    for (int st = 128; st > 0; st >>= 1) {
        if (threadIdx.x < st) {
            sh0[threadIdx.x] += sh0[threadIdx.x + st];
            sh1[threadIdx.x] += sh1[threadIdx.x + st];
        }
        __syncthreads();
    }
    if (threadIdx.x == 0) {
        float inv = 1.f / (NB * LSEQ);
        float mu = sh0[0] * inv;
        float var = sh1[0] * inv - mu * mu;
        mv[o] = mu; mv[128 + o] = var;
    }
}

__global__ void bn_apply(const float* __restrict__ y2, const float* __restrict__ mv,
                         const float* __restrict__ gamma, const float* __restrict__ beta,
                         float* __restrict__ out)
{
    int idx = blockIdx.x * blockDim.x + threadIdx.x;
    if (idx >= NB*128*LSEQ) return;
    int o = (idx >> 12) & 127;
    float mu = mv[o], var = mv[128 + o];
    float v = (y2[idx] - mu) * rsqrtf(var + 1e-5f) * gamma[o] + beta[o];
    out[idx] = 0.5f * v * (1.f + erff(v * 0.70710678118654752440f));
}

// ---------------- launch ----------------
extern "C" void kernel_launch(void* const* d_in, const int* in_sizes, int n_in,
                              void* d_out, int out_size)
{
    const float* x        = (const float*)d_in[0];
    const float* skip     = (const float*)d_in[1];
    const float* up_w     = (const float*)d_in[2];
    const float* up_b     = (const float*)d_in[3];
    const float* in_proj  = (const float*)d_in[4];
    const float* c1w      = (const float*)d_in[5];
    const float* c1b      = (const float*)d_in[6];
    const float* xproj    = (const float*)d_in[7];
    const float* dtw      = (const float*)d_in[8];
    const float* dtb      = (const float*)d_in[9];
    const float* A_log    = (const float*)d_in[10];
    const float* Dp       = (const float*)d_in[11];
    const float* outw     = (const float*)d_in[12];
    const float* cw       = (const float*)d_in[13];
    const float* cb       = (const float*)d_in[14];
    const float* bng      = (const float*)d_in[15];
    const float* bnb      = (const float*)d_in[16];
    float* out = (float*)d_out;

    float *xc, *xi, *z, *u, *dbc, *dtv, *y, *xr, *y2, *mv, *S, *hs, *sd;
    float *wt1, *wt2, *wt3;
    cudaGetSymbolAddress((void**)&xc,  g_xc);
    cudaGetSymbolAddress((void**)&xi,  g_xi);
    cudaGetSymbolAddress((void**)&z,   g_z);
    cudaGetSymbolAddress((void**)&u,   g_u);
    cudaGetSymbolAddress((void**)&dbc, g_dbc);
    cudaGetSymbolAddress((void**)&dtv, g_dt);
    cudaGetSymbolAddress((void**)&y,   g_y);
    cudaGetSymbolAddress((void**)&xr,  g_xr);
    cudaGetSymbolAddress((void**)&y2,  g_y2);
    cudaGetSymbolAddress((void**)&mv,  g_mv);
    cudaGetSymbolAddress((void**)&S,   g_S);
    cudaGetSymbolAddress((void**)&hs,  g_hs);
    cudaGetSymbolAddress((void**)&sd,  g_sd);
    cudaGetSymbolAddress((void**)&wt1, g_wt1);
    cudaGetSymbolAddress((void**)&wt2, g_wt2);
    cudaGetSymbolAddress((void**)&wt3, g_wt3);

    // 0) one-time weight transposes (cheap; must be in-graph for determinism)
    transp<<<dim3(256/32, 1024/32), dim3(32, 8)>>>(in_proj, wt1, 1024, 256);
    transp<<<dim3(512/32,  256/32), dim3(32, 8)>>>(outw,    wt2,  256, 512);
    transp<<<dim3(512/32,        2), dim3(32, 8)>>>(xproj,   wt3,   48, 512);

    // 1) upsample GEMM: C[512,1024] = up_w^T * x[b]
    gemm128<EpiUp><<<dim3(8, 4, NB), 256>>>(
        up_w, 512, 0, x, 1024, (long)256*1024, 512, 1024, 256, EpiUp{xc, up_b});

    // 2) skip concat
    copy_skip<<<(NB*128*LSEQ + 255)/256, 256>>>(skip, xc);

    // 3) in_proj GEMM: C[4096,1024] = xc^T * in_proj^T (both k-major)
    gemm128<EpiXZ><<<dim3(8, 32, NB), 256>>>(
        xc, LSEQ, (long)DM*LSEQ, wt1, 1024, 0, LSEQ, 2*DI, DM, EpiXZ{xi, z});

    // 4) depthwise conv1d + silu
    conv1d_kernel<<<dim3(LSEQ/128, DI/32, NB), 256>>>(xi, c1w, c1b, u);

    // 5) x_proj GEMM: C[4096,48] per batch = u^T * xproj^T
    gemm_k<true, false, EpiDbc><<<dim3(1, 64, NB), 256>>>(
        u, LSEQ, (long)DI*LSEQ, wt3, 48, 0, LSEQ, 48, DI, EpiDbc{dbc});

    // 6) dt = softplus(dbc[:16]^T @ dtw^T + dtb)
    dt_kernel<<<NB*LSEQ/64, 256>>>(dbc, dtw, dtb, dtv);

    // 7) chunked selective scan
    scan_pass1<<<dim3(NCH, NB*DI/8), 128>>>(dtv, u, dbc, A_log, S, sd);
    scan_pass2<<<NB*DI/8, 128>>>(S, sd, A_log, hs);
    scan_pass3<<<dim3(NCH, NB*DI/8), 128>>>(dtv, u, dbc, z, A_log, Dp, hs, y);

    // 8) out_proj GEMM + residual
    gemm128<EpiOut><<<dim3(2, 32, NB), 256>>>(
        y, LSEQ, (long)DI*LSEQ, wt2, 256, 0, LSEQ, DM, DI, EpiOut{xc, xr});

    // 9) 3x3 conv
    conv3_kernel<<<dim3(16, 8, NB), 256>>>(xr, cw, cb, y2);

    // 10) batchnorm stats
    bn_stats<<<128, 256>>>(y2, mv);

    // 11) batchnorm apply + gelu
    bn_apply<<<(NB*128*LSEQ + 255)/256, 256>>>(y2, mv, bng, bnb, out);
}